// round 12
// baseline (speedup 1.0000x reference)
#include <cuda_runtime.h>
#include <cuda_fp16.h>
#include <math.h>

#define NN 100000
#define IN_DIM 256
#define HD 64
#define HDH (HD/2)
#define NA 4
#define NE 1600000
#define NT 4
#define NCLS 8
#define NH (NN*HD)
#define NB 98
#define SB 98

// ---------------- scratch ----------------
__device__ __half2 g_xp[NN * HD];      // interleaved (x0,x1)
__device__ __half2 g_sh[NN * HDH];     // s1
__device__ __half2 g_th[NN * HDH];     // t1
__device__ __half2 g_s2h[NN * HDH];    // s2
__device__ __half2 g_S0h[NA][NN * HDH];
__device__ __half2 g_S1h[NA][NN * HDH];
__device__ __half2 g_T0h[NA][NN * HDH];
__device__ __half2 g_T1h[2][NN * HDH];
__device__ int     g_rowptr[NA][NN + 1];
__device__ int     g_wp[NA][NN];
__device__ int     g_scan[NA][NN];
__device__ int     g_bsum[NA][NB + 2];
__device__ int2    g_edge[NA][NE];
__device__ float   g_coef[32];
__device__ int     g_btc[NT][SB];
__device__ int     g_toff[NT][SB];
__device__ int     g_order[NN];

// ---------------- coefficients ----------------
__device__ __forceinline__ void softmax_scaled(const float* p, int n, float scale, float* o) {
    float m = -1e30f;
    for (int i = 0; i < n; i++) m = fmaxf(m, p[i]);
    float s = 0.f;
    for (int i = 0; i < n; i++) { o[i] = expf(p[i] - m); s += o[i]; }
    float inv = scale / s;
    for (int i = 0; i < n; i++) o[i] *= inv;
}

__global__ void coef_kernel(const float* as_seq0, const float* as_last_seq0,
                            const float* as_res0, const float* as_last_res0,
                            const float* as_seq1, const float* as_last_seq1,
                            const float* as_last_res1) {
    softmax_scaled(as_seq0 + 0, 3, 1.f / 3.f, &g_coef[0]);
    softmax_scaled(as_seq0 + 3, 3, 1.f / 3.f, &g_coef[3]);
    softmax_scaled(as_res0, 4, 1.f / 4.f, &g_coef[6]);
    softmax_scaled(as_last_seq0, 2, 1.f / 2.f, &g_coef[10]);
    softmax_scaled(as_last_res0 + 0, 3, 1.f / 3.f, &g_coef[12]);
    softmax_scaled(as_last_res0 + 3, 3, 1.f / 3.f, &g_coef[15]);
    softmax_scaled(as_seq1, 3, 1.f / 3.f, &g_coef[18]);
    softmax_scaled(as_last_seq1, 2, 1.f / 2.f, &g_coef[21]);
    softmax_scaled(as_last_res1, 3, 1.f / 3.f, &g_coef[23]);
}

// ---------------- type sort ----------------
__global__ void __launch_bounds__(1024) type_count_kernel(const int* __restrict__ types) {
    int b = blockIdx.x;
    int i = b * 1024 + threadIdx.x;
    int w = threadIdx.x >> 5, lane = threadIdx.x & 31;
    int t = (i < NN) ? types[i] : -1;
    __shared__ int wcnt[NT][32];
#pragma unroll
    for (int tt = 0; tt < NT; tt++) {
        unsigned m = __ballot_sync(0xffffffffu, t == tt);
        if (lane == 0) wcnt[tt][w] = __popc(m);
    }
    __syncthreads();
    if (threadIdx.x < NT) {
        int s = 0;
        for (int k = 0; k < 32; k++) s += wcnt[threadIdx.x][k];
        g_btc[threadIdx.x][b] = s;
    }
}

__global__ void type_offsets_kernel() {
    int run = 0;
    for (int t = 0; t < NT; t++)
        for (int b = 0; b < SB; b++) {
            int c = g_btc[t][b];
            g_toff[t][b] = run;
            run += c;
        }
}

__global__ void __launch_bounds__(1024) type_scatter_kernel(const int* __restrict__ types) {
    int b = blockIdx.x;
    int i = b * 1024 + threadIdx.x;
    int w = threadIdx.x >> 5, lane = threadIdx.x & 31;
    int t = (i < NN) ? types[i] : -1;
    __shared__ int wcnt[NT][32];
    int lr = 0;
#pragma unroll
    for (int tt = 0; tt < NT; tt++) {
        unsigned m = __ballot_sync(0xffffffffu, t == tt);
        if (lane == 0) wcnt[tt][w] = __popc(m);
        if (t == tt) lr = __popc(m & ((1u << lane) - 1u));
    }
    __syncthreads();
    if (threadIdx.x < NT * 32) {
        int tt = threadIdx.x >> 5, k = threadIdx.x & 31;
        int v = wcnt[tt][k];
#pragma unroll
        for (int off = 1; off < 32; off <<= 1) {
            int u = __shfl_up_sync(0xffffffffu, v, off);
            if (k >= off) v += u;
        }
        wcnt[tt][k] = v;
    }
    __syncthreads();
    if (t >= 0) {
        int wpre = (w > 0) ? wcnt[t][w - 1] : 0;
        g_order[g_toff[t][b] + wpre + lr] = i;
    }
}

// ---------------- CSR build ----------------
__global__ void zero_wp_kernel() {
    int i = blockIdx.x * blockDim.x + threadIdx.x;
    if (i < NA * NN) ((int*)g_wp)[i] = 0;
}

__global__ void hist_kernel(const int* __restrict__ rows) {
    int i = blockIdx.x * blockDim.x + threadIdx.x;
    if (i >= NA * NE) return;
    int a = i / NE;
    atomicAdd(&g_wp[a][rows[i]], 1);
}

__global__ void __launch_bounds__(1024) scan_local_kernel() {
    int a = blockIdx.y;
    int i = blockIdx.x * 1024 + threadIdx.x;
    int lane = threadIdx.x & 31;
    int w = threadIdx.x >> 5;
    int c = (i < NN) ? g_wp[a][i] : 0;
    int v = c;
#pragma unroll
    for (int off = 1; off < 32; off <<= 1) {
        int t = __shfl_up_sync(0xffffffffu, v, off);
        if (lane >= off) v += t;
    }
    __shared__ int wsum[32];
    if (lane == 31) wsum[w] = v;
    __syncthreads();
    if (w == 0) {
        int s = wsum[lane];
#pragma unroll
        for (int off = 1; off < 32; off <<= 1) {
            int t = __shfl_up_sync(0xffffffffu, s, off);
            if (lane >= off) s += t;
        }
        wsum[lane] = s;
    }
    __syncthreads();
    int incl = v + (w > 0 ? wsum[w - 1] : 0);
    if (i < NN) g_scan[a][i] = incl;
    if (threadIdx.x == 1023) g_bsum[a][blockIdx.x] = incl;
}

__global__ void scan_sums_kernel() {
    int a = threadIdx.x;
    if (a >= NA) return;
    int run = 0;
    for (int b = 0; b < NB; b++) {
        int t = g_bsum[a][b];
        g_bsum[a][b] = run;
        run += t;
    }
}

__global__ void __launch_bounds__(1024) scan_add_kernel() {
    int a = blockIdx.y;
    int i = blockIdx.x * 1024 + threadIdx.x;
    if (i >= NN) return;
    int incl = g_scan[a][i] + g_bsum[a][blockIdx.x];
    int c = g_wp[a][i];
    g_rowptr[a][i + 1] = incl;
    g_wp[a][i] = incl - c;
    if (i == 0) g_rowptr[a][0] = 0;
}

__global__ void scatter_kernel(const int* __restrict__ rows, const int* __restrict__ cols,
                               const float* __restrict__ vals) {
    int i = blockIdx.x * blockDim.x + threadIdx.x;
    if (i >= NA * NE) return;
    int a = i / NE;
    int r = rows[i];
    int p = atomicAdd(&g_wp[a][r], 1);
    g_edge[a][p] = make_int2(cols[i], __float_as_int(vals[i]));
}

// ---------------- fused dense projection: hid then x0/x1 (4 nodes per warp) ----------------
__global__ void __launch_bounds__(256) proj_kernel(const float* __restrict__ feats,
                                                   const int* __restrict__ types,
                                                   const float* __restrict__ W,
                                                   const float* __restrict__ b,
                                                   const float* __restrict__ W0,
                                                   const float* __restrict__ b0,
                                                   const float* __restrict__ W1,
                                                   const float* __restrict__ b1) {
    __shared__ float sf[8][4][IN_DIM];   // feats, then hid reuses [0..63]
    int wid = (blockIdx.x * blockDim.x + threadIdx.x) >> 5;
    int lane = threadIdx.x & 31;
    int wl = threadIdx.x >> 5;
    int base = wid * 4;
    if (base >= NN) return;
    int cnt = min(4, NN - base);
    int nidx[4], tt[4];
#pragma unroll
    for (int k = 0; k < 4; k++) {
        int kk = (k < cnt) ? k : cnt - 1;
        nidx[k] = g_order[base + kk];
        tt[k] = types[nidx[k]];
    }
    for (int k = 0; k < cnt; k++)
        for (int d = lane; d < IN_DIM; d += 32) sf[wl][k][d] = feats[nidx[k] * IN_DIM + d];
    __syncwarp();
    int j = 2 * lane;
    float hv[4][2];
    if (cnt == 4 && tt[0] == tt[3]) {
        const float* Wt = W + tt[0] * IN_DIM * HD;
        float acc[4][2] = {};
#pragma unroll 4
        for (int d = 0; d < IN_DIM; d++) {
            float2 wv = *(const float2*)(Wt + d * HD + j);
#pragma unroll
            for (int k = 0; k < 4; k++) {
                float f = sf[wl][k][d];
                acc[k][0] += f * wv.x;
                acc[k][1] += f * wv.y;
            }
        }
        float b0v = b[tt[0] * HD + j], b1v = b[tt[0] * HD + j + 1];
#pragma unroll
        for (int k = 0; k < 4; k++) {
            hv[k][0] = acc[k][0] + b0v;
            hv[k][1] = acc[k][1] + b1v;
        }
    } else {
        for (int k = 0; k < cnt; k++) {
            const float* Wt = W + tt[k] * IN_DIM * HD;
            float a0 = 0.f, a1 = 0.f;
#pragma unroll 4
            for (int d = 0; d < IN_DIM; d++) {
                float f = sf[wl][k][d];
                float2 wv = *(const float2*)(Wt + d * HD + j);
                a0 += f * wv.x;
                a1 += f * wv.y;
            }
            hv[k][0] = a0 + b[tt[k] * HD + j];
            hv[k][1] = a1 + b[tt[k] * HD + j + 1];
        }
    }
    __syncwarp();   // all reads of feats done
    for (int k = 0; k < cnt; k++) {
        sf[wl][k][j] = hv[k][0];
        sf[wl][k][j + 1] = hv[k][1];
    }
    __syncwarp();
    // x0/x1 from hid rows in smem
    float a0[4] = {}, a1[4] = {}, c0[4] = {}, c1[4] = {};
#pragma unroll 4
    for (int d = 0; d < HD; d++) {
        float2 w0 = *(const float2*)(W0 + d * HD + j);
        float2 w1 = *(const float2*)(W1 + d * HD + j);
#pragma unroll
        for (int k = 0; k < 4; k++) {
            float f = sf[wl][k][d];
            a0[k] += f * w0.x; a1[k] += f * w0.y;
            c0[k] += f * w1.x; c1[k] += f * w1.y;
        }
    }
    float b00 = b0[j], b01 = b0[j + 1], b10 = b1[j], b11 = b1[j + 1];
    for (int k = 0; k < cnt; k++) {
        int n = nidx[k];
        g_xp[n * HD + j]     = __floats2half2_rn(a0[k] + b00, c0[k] + b10);
        g_xp[n * HD + j + 1] = __floats2half2_rn(a1[k] + b01, c1[k] + b11);
    }
}

// ---------------- stage 1: S0/T0 all adjacencies + s1/t1 epilogue ----------------
__global__ void __launch_bounds__(256) spmm_pair_all_kernel() {
    int r = (blockIdx.x * blockDim.x + threadIdx.x) >> 5;
    int lane = threadIdx.x & 31;
    if (r >= NN) return;
    float s1a = 0.f, s1b = 0.f, t1a = 0.f, t1b = 0.f;
#pragma unroll
    for (int a = 0; a < NA; a++) {
        const int2* __restrict__ ee = g_edge[a];
        int s = g_rowptr[a][r];
        int e = g_rowptr[a][r + 1];
        float a0 = 0.f, a1 = 0.f, b0 = 0.f, b1 = 0.f;
        int i = s;
        for (; i + 3 < e; i += 4) {
            int2 e0 = ee[i], e1 = ee[i + 1], e2 = ee[i + 2], e3 = ee[i + 3];
            uint2 p0 = *(const uint2*)(g_xp + e0.x * HD + 2 * lane);
            uint2 p1 = *(const uint2*)(g_xp + e1.x * HD + 2 * lane);
            uint2 p2 = *(const uint2*)(g_xp + e2.x * HD + 2 * lane);
            uint2 p3 = *(const uint2*)(g_xp + e3.x * HD + 2 * lane);
            float v0 = __int_as_float(e0.y), v1 = __int_as_float(e1.y);
            float v2 = __int_as_float(e2.y), v3 = __int_as_float(e3.y);
            float2 f;
            f = __half22float2(*(__half2*)&p0.x); a0 += v0 * f.x; b0 += v0 * f.y;
            f = __half22float2(*(__half2*)&p0.y); a1 += v0 * f.x; b1 += v0 * f.y;
            f = __half22float2(*(__half2*)&p1.x); a0 += v1 * f.x; b0 += v1 * f.y;
            f = __half22float2(*(__half2*)&p1.y); a1 += v1 * f.x; b1 += v1 * f.y;
            f = __half22float2(*(__half2*)&p2.x); a0 += v2 * f.x; b0 += v2 * f.y;
            f = __half22float2(*(__half2*)&p2.y); a1 += v2 * f.x; b1 += v2 * f.y;
            f = __half22float2(*(__half2*)&p3.x); a0 += v3 * f.x; b0 += v3 * f.y;
            f = __half22float2(*(__half2*)&p3.y); a1 += v3 * f.x; b1 += v3 * f.y;
        }
        for (; i < e; i++) {
            int2 e0 = ee[i];
            float v0 = __int_as_float(e0.y);
            uint2 p0 = *(const uint2*)(g_xp + e0.x * HD + 2 * lane);
            float2 f00 = __half22float2(*(__half2*)&p0.x);
            float2 f01 = __half22float2(*(__half2*)&p0.y);
            a0 += v0 * f00.x; b0 += v0 * f00.y;
            a1 += v0 * f01.x; b1 += v0 * f01.y;
        }
        int idx = r * HDH + lane;
        g_S0h[a][idx] = __floats2half2_rn(a0, a1);
        g_T0h[a][idx] = __floats2half2_rn(b0, b1);
        if (a < 3) {
            float cs = g_coef[a], ct = g_coef[18 + a];
            s1a += cs * a0; s1b += cs * a1;
            t1a += ct * b0; t1b += ct * b1;
        }
    }
    int idx = r * HDH + lane;
    g_sh[idx] = __floats2half2_rn(s1a, s1b);
    g_th[idx] = __floats2half2_rn(t1a, t1b);
}

// ---------------- stage 2: S1 (4 adj) + T1 (adj 0,1 merged) + s2 epilogue ----------------
__global__ void __launch_bounds__(256) spmm_mid_all_kernel() {
    int r = (blockIdx.x * blockDim.x + threadIdx.x) >> 5;
    int lane = threadIdx.x & 31;
    if (r >= NN) return;
    int idx = r * HDH + lane;
    float s2a = 0.f, s2b = 0.f;
#pragma unroll
    for (int a = 0; a < NA; a++) {
        const int2* __restrict__ ee = g_edge[a];
        int s = g_rowptr[a][r];
        int e = g_rowptr[a][r + 1];
        float a0 = 0.f, a1 = 0.f, u0 = 0.f, u1 = 0.f;
        int i = s;
        if (a < 2) {
            for (; i + 1 < e; i += 2) {
                int2 e0 = ee[i], e1 = ee[i + 1];
                float v0 = __int_as_float(e0.y), v1 = __int_as_float(e1.y);
                float2 f0 = __half22float2(g_sh[e0.x * HDH + lane]);
                float2 f1 = __half22float2(g_sh[e1.x * HDH + lane]);
                float2 g0 = __half22float2(g_th[e0.x * HDH + lane]);
                float2 g1 = __half22float2(g_th[e1.x * HDH + lane]);
                a0 += v0 * f0.x + v1 * f1.x;
                a1 += v0 * f0.y + v1 * f1.y;
                u0 += v0 * g0.x + v1 * g1.x;
                u1 += v0 * g0.y + v1 * g1.y;
            }
            if (i < e) {
                int2 e0 = ee[i];
                float v0 = __int_as_float(e0.y);
                float2 f0 = __half22float2(g_sh[e0.x * HDH + lane]);
                float2 g0 = __half22float2(g_th[e0.x * HDH + lane]);
                a0 += v0 * f0.x; a1 += v0 * f0.y;
                u0 += v0 * g0.x; u1 += v0 * g0.y;
            }
            g_T1h[a][idx] = __floats2half2_rn(u0, u1);
        } else {
            for (; i + 3 < e; i += 4) {
                int2 e0 = ee[i], e1 = ee[i + 1], e2 = ee[i + 2], e3 = ee[i + 3];
                float v0 = __int_as_float(e0.y), v1 = __int_as_float(e1.y);
                float v2 = __int_as_float(e2.y), v3 = __int_as_float(e3.y);
                float2 f0 = __half22float2(g_sh[e0.x * HDH + lane]);
                float2 f1 = __half22float2(g_sh[e1.x * HDH + lane]);
                float2 f2 = __half22float2(g_sh[e2.x * HDH + lane]);
                float2 f3 = __half22float2(g_sh[e3.x * HDH + lane]);
                a0 += v0 * f0.x + v1 * f1.x + v2 * f2.x + v3 * f3.x;
                a1 += v0 * f0.y + v1 * f1.y + v2 * f2.y + v3 * f3.y;
            }
            for (; i < e; i++) {
                int2 e0 = ee[i];
                float v0 = __int_as_float(e0.y);
                float2 f0 = __half22float2(g_sh[e0.x * HDH + lane]);
                a0 += v0 * f0.x;
                a1 += v0 * f0.y;
            }
        }
        g_S1h[a][idx] = __floats2half2_rn(a0, a1);
        if (a < 3) {
            float q = g_coef[3 + a];
            s2a += q * a0; s2b += q * a1;
        }
    }
#pragma unroll
    for (int a = 0; a < NA; a++) {
        float2 h = __half22float2(g_S0h[a][idx]);
        float p = g_coef[6 + a];
        s2a += p * h.x; s2b += p * h.y;
    }
    g_s2h[idx] = __floats2half2_rn(s2a, s2b);
}

// ---------------- helpers ----------------
__device__ __forceinline__ float warp_sum(float v) {
#pragma unroll
    for (int off = 16; off; off >>= 1) v += __shfl_xor_sync(0xffffffffu, v, off);
    return v;
}

__device__ __forceinline__ float gelu_exact(float x) {
    return 0.5f * x * (1.f + erff(x * 0.70710678118654752f));
}

// ---------------- stage 3: S2 in-register + LN/GELU + attention + classifier ----------------
__global__ void __launch_bounds__(256) spmm_out_final_kernel(const float* __restrict__ aW1,
                                                             const float* __restrict__ ab1,
                                                             const float* __restrict__ aW2,
                                                             const float* __restrict__ ab2,
                                                             const float* __restrict__ cW,
                                                             const float* __restrict__ cb,
                                                             float* __restrict__ out) {
    __shared__ float sh0[8][HD];
    __shared__ float sh1[8][HD];
    int r = (blockIdx.x * blockDim.x + threadIdx.x) >> 5;
    int lane = threadIdx.x & 31;
    int wl = threadIdx.x >> 5;
    if (r >= NN) return;
    int idx = r * HDH + lane;
    const int sub[3] = {0, 1, 3};
    float S2v[2][2];
#pragma unroll
    for (int a = 0; a < 2; a++) {
        const int2* __restrict__ ee = g_edge[a];
        int s = g_rowptr[a][r];
        int e = g_rowptr[a][r + 1];
        float a0 = 0.f, a1 = 0.f;
        int i = s;
        for (; i + 1 < e; i += 2) {
            int2 e0 = ee[i], e1 = ee[i + 1];
            float v0 = __int_as_float(e0.y), v1 = __int_as_float(e1.y);
            float2 f0 = __half22float2(g_s2h[e0.x * HDH + lane]);
            float2 f1 = __half22float2(g_s2h[e1.x * HDH + lane]);
            a0 += v0 * f0.x + v1 * f1.x;
            a1 += v0 * f0.y + v1 * f1.y;
        }
        if (i < e) {
            int2 e0 = ee[i];
            float v0 = __int_as_float(e0.y);
            float2 f0 = __half22float2(g_s2h[e0.x * HDH + lane]);
            a0 += v0 * f0.x;
            a1 += v0 * f0.y;
        }
        S2v[a][0] = a0; S2v[a][1] = a1;
    }
    // cell 0 LN+GELU -> sh0
    {
        float ls0 = g_coef[10], ls1 = g_coef[11];
        float u0 = ls0 * S2v[0][0] + ls1 * S2v[1][0];
        float u1 = ls0 * S2v[0][1] + ls1 * S2v[1][1];
#pragma unroll
        for (int k = 0; k < 3; k++) {
            int j = sub[k];
            float cA = g_coef[12 + k], cB = g_coef[15 + k];
            float2 h0 = __half22float2(g_S0h[j][idx]);
            float2 h1 = __half22float2(g_S1h[j][idx]);
            u0 += cA * h0.x + cB * h1.x;
            u1 += cA * h0.y + cB * h1.y;
        }
        float mean = warp_sum(u0 + u1) * (1.f / 64.f);
        float d0 = u0 - mean, d1 = u1 - mean;
        float var = warp_sum(d0 * d0 + d1 * d1) * (1.f / 64.f);
        float inv = rsqrtf(var + 1e-5f);
        sh0[wl][2 * lane] = gelu_exact(d0 * inv);
        sh0[wl][2 * lane + 1] = gelu_exact(d1 * inv);
    }
    // cell 1 LN+GELU -> sh1
    {
        float ls0 = g_coef[21], ls1 = g_coef[22];
        float2 t0 = __half22float2(g_T1h[0][idx]);
        float2 t1 = __half22float2(g_T1h[1][idx]);
        float u0 = ls0 * t0.x + ls1 * t1.x;
        float u1 = ls0 * t0.y + ls1 * t1.y;
#pragma unroll
        for (int k = 0; k < 3; k++) {
            int j = sub[k];
            float cA = g_coef[23 + k];
            float2 h0 = __half22float2(g_T0h[j][idx]);
            u0 += cA * h0.x;
            u1 += cA * h0.y;
        }
        float mean = warp_sum(u0 + u1) * (1.f / 64.f);
        float d0 = u0 - mean, d1 = u1 - mean;
        float var = warp_sum(d0 * d0 + d1 * d1) * (1.f / 64.f);
        float inv = rsqrtf(var + 1e-5f);
        sh1[wl][2 * lane] = gelu_exact(d0 * inv);
        sh1[wl][2 * lane + 1] = gelu_exact(d1 * inv);
    }
    __syncwarp();
    // semantic attention
    float t0a = ab1[lane], t0b = ab1[32 + lane];
    float t1a = ab1[lane], t1b = ab1[32 + lane];
#pragma unroll 8
    for (int d = 0; d < HD; d++) {
        float wa = aW1[d * HD + lane], wb = aW1[d * HD + 32 + lane];
        t0a += sh0[wl][d] * wa; t0b += sh0[wl][d] * wb;
        t1a += sh1[wl][d] * wa; t1b += sh1[wl][d] * wb;
    }
    t0a = tanhf(t0a); t0b = tanhf(t0b);
    t1a = tanhf(t1a); t1b = tanhf(t1b);
    float z0 = t0a * aW2[lane] + t0b * aW2[32 + lane];
    float z1 = t1a * aW2[lane] + t1b * aW2[32 + lane];
    z0 = warp_sum(z0) + ab2[0];
    z1 = warp_sum(z1) + ab2[0];
    float m = fmaxf(z0, z1);
    float e0 = expf(z0 - m), e1 = expf(z1 - m);
    float w0 = e0 / (e0 + e1), w1 = 1.f - w0;
    float ca = w0 * sh0[wl][lane] + w1 * sh1[wl][lane];
    float cb2 = w0 * sh0[wl][32 + lane] + w1 * sh1[wl][32 + lane];
    __syncwarp();
    sh0[wl][lane] = ca;
    sh0[wl][32 + lane] = cb2;
    __syncwarp();
    if (lane < NCLS) {
        float acc = cb[lane];
#pragma unroll
        for (int d = 0; d < HD; d++) acc += sh0[wl][d] * cW[d * NCLS + lane];
        out[r * NCLS + lane] = acc;
    }
}

// ---------------- launcher ----------------
extern "C" void kernel_launch(void* const* d_in, const int* in_sizes, int n_in,
                              void* d_out, int out_size) {
    const float* node_feats   = (const float*)d_in[0];
    const int*   node_types   = (const int*)d_in[1];
    const int*   adj_rows     = (const int*)d_in[2];
    const int*   adj_cols     = (const int*)d_in[3];
    const float* adj_vals     = (const float*)d_in[4];
    const float* type_W       = (const float*)d_in[5];
    const float* type_b       = (const float*)d_in[6];
    const float* affine_W0    = (const float*)d_in[7];
    const float* affine_b0    = (const float*)d_in[8];
    const float* affine_W1    = (const float*)d_in[9];
    const float* affine_b1    = (const float*)d_in[10];
    const float* as_seq0      = (const float*)d_in[11];
    const float* as_last_seq0 = (const float*)d_in[12];
    const float* as_res0      = (const float*)d_in[13];
    const float* as_last_res0 = (const float*)d_in[14];
    const float* as_seq1      = (const float*)d_in[15];
    const float* as_last_seq1 = (const float*)d_in[16];
    const float* as_last_res1 = (const float*)d_in[17];
    const float* attn1_W      = (const float*)d_in[18];
    const float* attn1_b      = (const float*)d_in[19];
    const float* attn2_W      = (const float*)d_in[20];
    const float* attn2_b      = (const float*)d_in[21];
    const float* cls_W        = (const float*)d_in[22];
    const float* cls_b        = (const float*)d_in[23];
    float* out = (float*)d_out;

    const int WARP_BLOCKS = (NN * 32 + 255) / 256;
    const int WARP4_BLOCKS = ((NN + 3) / 4 * 32 + 255) / 256;
    const int EDGE_BLOCKS = (NA * NE + 255) / 256;

    coef_kernel<<<1, 1>>>(as_seq0, as_last_seq0, as_res0, as_last_res0,
                          as_seq1, as_last_seq1, as_last_res1);

    type_count_kernel<<<SB, 1024>>>(node_types);
    type_offsets_kernel<<<1, 1>>>();
    type_scatter_kernel<<<SB, 1024>>>(node_types);

    zero_wp_kernel<<<(NA * NN + 255) / 256, 256>>>();
    hist_kernel<<<EDGE_BLOCKS, 256>>>(adj_rows);
    scan_local_kernel<<<dim3(NB, NA), 1024>>>();
    scan_sums_kernel<<<1, 32>>>();
    scan_add_kernel<<<dim3(NB, NA), 1024>>>();
    scatter_kernel<<<EDGE_BLOCKS, 256>>>(adj_rows, adj_cols, adj_vals);

    proj_kernel<<<WARP4_BLOCKS, 256>>>(node_feats, node_types, type_W, type_b,
                                       affine_W0, affine_b0, affine_W1, affine_b1);

    spmm_pair_all_kernel<<<WARP_BLOCKS, 256>>>();
    spmm_mid_all_kernel<<<WARP_BLOCKS, 256>>>();
    spmm_out_final_kernel<<<WARP_BLOCKS, 256>>>(attn1_W, attn1_b, attn2_W, attn2_b,
                                                cls_W, cls_b, out);
}